// round 1
// baseline (speedup 1.0000x reference)
#include <cuda_runtime.h>
#include <math.h>

#define THREADS 256
#define BLOCKS  1216          // 152 SMs * 8
#define CAND_CAP (1 << 20)
#define CAND_T   0.00390625f  // 2^-8

// ---------------- device-global scratch (no allocations allowed) ----------------
__device__ double             g_s1[2];       // sum p   over non-positive elems
__device__ double             g_s2[2];       // sum p^2 over non-positive elems
__device__ unsigned long long g_k[2];        // count   of non-positive elems
__device__ unsigned int       g_minkey[2];   // ordered-uint key of min(predict | target==1)
__device__ int                g_candcnt[2];  // # of non-pos elems with p < CAND_T
__device__ int                g_flag;        // 1 => candidate path invalid, use fallback
__device__ double             g_corr[2];     // fallback correction sums
__device__ float              g_margin;
__device__ float              g_cand[2][CAND_CAP];

// ---------------- ordered-uint key for float atomicMin (handles any sign) -------
__device__ __forceinline__ unsigned int fkey(float f) {
    unsigned int b = __float_as_uint(f);
    return (b & 0x80000000u) ? ~b : (b | 0x80000000u);
}
__device__ __forceinline__ float funkey(unsigned int k) {
    unsigned int b = (k & 0x80000000u) ? (k & 0x7fffffffu) : ~k;
    return __uint_as_float(b);
}

// ---------------- kernel 0: reset accumulators (graph replays must be clean) ----
__global__ void init_kernel() {
    if (threadIdx.x == 0) {
        #pragma unroll
        for (int s = 0; s < 2; s++) {
            g_s1[s] = 0.0; g_s2[s] = 0.0; g_k[s] = 0ull;
            g_minkey[s] = 0xFF800000u;   // fkey(+inf)
            g_candcnt[s] = 0;
            g_corr[s] = 0.0;
        }
        g_flag = 0;
        g_margin = 0.0f;
    }
}

// ---------------- kernel 1: single fused pass over all 4 tensors ----------------
// Per lane (tensor s): if target==1 -> track min(predict)
//                      else         -> s1 += p, s2 += p*p, k++, and if p < CAND_T
//                                      append p to candidate buffer.
#define PROC(S, P, T)                                                        \
    do {                                                                     \
        float _p = (P), _t = (T);                                            \
        if (fabsf(_t - 1.0f) < 1e-5f) {                                      \
            mn##S = fminf(mn##S, _p);                                        \
        } else {                                                             \
            s1##S += _p;                                                     \
            s2##S = fmaf(_p, _p, s2##S);                                     \
            k##S++;                                                          \
            if (_p < CAND_T) {                                               \
                int _i = atomicAdd(&g_candcnt[S], 1);                        \
                if (_i < CAND_CAP) g_cand[S][_i] = _p;                       \
            }                                                                \
        }                                                                    \
    } while (0)

__global__ void __launch_bounds__(THREADS) pass1_kernel(
    const float4* __restrict__ ap, const float4* __restrict__ at,
    const float4* __restrict__ bp, const float4* __restrict__ bt,
    int n4, int ntail)
{
    float s10 = 0.f, s20 = 0.f, mn0 = __int_as_float(0x7f800000);
    float s11 = 0.f, s21 = 0.f, mn1 = __int_as_float(0x7f800000);
    int   k0 = 0, k1 = 0;

    const int stride = gridDim.x * blockDim.x;
    for (int i = blockIdx.x * blockDim.x + threadIdx.x; i < n4; i += stride) {
        float4 pa = ap[i], ta = at[i], pb = bp[i], tb = bt[i];
        PROC(0, pa.x, ta.x); PROC(0, pa.y, ta.y);
        PROC(0, pa.z, ta.z); PROC(0, pa.w, ta.w);
        PROC(1, pb.x, tb.x); PROC(1, pb.y, tb.y);
        PROC(1, pb.z, tb.z); PROC(1, pb.w, tb.w);
    }
    // scalar tail (n not divisible by 4)
    if (blockIdx.x == 0 && threadIdx.x < ntail) {
        const float* apf = reinterpret_cast<const float*>(ap);
        const float* atf = reinterpret_cast<const float*>(at);
        const float* bpf = reinterpret_cast<const float*>(bp);
        const float* btf = reinterpret_cast<const float*>(bt);
        int idx = n4 * 4 + threadIdx.x;
        PROC(0, apf[idx], atf[idx]);
        PROC(1, bpf[idx], btf[idx]);
    }

    // ---- warp reduce ----
    #pragma unroll
    for (int o = 16; o > 0; o >>= 1) {
        s10 += __shfl_down_sync(0xffffffffu, s10, o);
        s20 += __shfl_down_sync(0xffffffffu, s20, o);
        k0  += __shfl_down_sync(0xffffffffu, k0,  o);
        mn0  = fminf(mn0, __shfl_down_sync(0xffffffffu, mn0, o));
        s11 += __shfl_down_sync(0xffffffffu, s11, o);
        s21 += __shfl_down_sync(0xffffffffu, s21, o);
        k1  += __shfl_down_sync(0xffffffffu, k1,  o);
        mn1  = fminf(mn1, __shfl_down_sync(0xffffffffu, mn1, o));
    }

    // ---- block reduce across warps ----
    __shared__ float sh_s1[2][THREADS / 32], sh_s2[2][THREADS / 32], sh_mn[2][THREADS / 32];
    __shared__ int   sh_k[2][THREADS / 32];
    int wid = threadIdx.x >> 5, lid = threadIdx.x & 31;
    if (lid == 0) {
        sh_s1[0][wid] = s10; sh_s2[0][wid] = s20; sh_mn[0][wid] = mn0; sh_k[0][wid] = k0;
        sh_s1[1][wid] = s11; sh_s2[1][wid] = s21; sh_mn[1][wid] = mn1; sh_k[1][wid] = k1;
    }
    __syncthreads();
    if (threadIdx.x == 0) {
        #pragma unroll
        for (int s = 0; s < 2; s++) {
            float S1 = 0.f, S2 = 0.f, MN = __int_as_float(0x7f800000);
            int K = 0;
            #pragma unroll
            for (int w = 0; w < THREADS / 32; w++) {
                S1 += sh_s1[s][w]; S2 += sh_s2[s][w];
                K  += sh_k[s][w];  MN  = fminf(MN, sh_mn[s][w]);
            }
            atomicAdd(&g_s1[s], (double)S1);
            atomicAdd(&g_s2[s], (double)S2);
            atomicAdd(&g_k[s],  (unsigned long long)K);
            atomicMin(&g_minkey[s], fkey(MN));
        }
    }
}

// ---------------- kernel 2: compute margin + (usually) final answer -------------
__global__ void __launch_bounds__(256) prep_kernel(float* out, double inv_n) {
    __shared__ double sh[256];
    __shared__ float  sh_m;
    __shared__ int    sh_valid;
    if (threadIdx.x == 0) {
        float sA = fminf(1.0f, funkey(g_minkey[0]));
        float sB = fminf(1.0f, funkey(g_minkey[1]));
        float m  = fminf(sA, sB);
        g_margin = m;
        int valid = (m <= CAND_T) && (g_candcnt[0] <= CAND_CAP) && (g_candcnt[1] <= CAND_CAP);
        g_flag  = valid ? 0 : 1;
        sh_m = m; sh_valid = valid;
    }
    __syncthreads();
    if (!sh_valid) return;    // fallback kernel will finish the job

    float m = sh_m;
    double corr[2];
    #pragma unroll
    for (int s = 0; s < 2; s++) {
        double c = 0.0;
        int cnt = min(g_candcnt[s], CAND_CAP);
        for (int i = threadIdx.x; i < cnt; i += 256) {
            float p = g_cand[s][i];
            if (p < m) { double d = (double)m - (double)p; c += 0.5 * d * d; }
        }
        sh[threadIdx.x] = c;
        __syncthreads();
        for (int o = 128; o > 0; o >>= 1) {
            if (threadIdx.x < o) sh[threadIdx.x] += sh[threadIdx.x + o];
            __syncthreads();
        }
        corr[s] = sh[0];
        __syncthreads();
    }
    if (threadIdx.x == 0) {
        double md = (double)m;
        #pragma unroll
        for (int s = 0; s < 2; s++) {
            double sum = 0.5 * g_s2[s] - md * g_s1[s]
                       + 0.5 * md * md * (double)g_k[s] - corr[s];
            out[s] = (float)(sum * inv_n);
        }
    }
}

// ---------------- kernel 3: exact fallback (early-exits when not needed) --------
__global__ void __launch_bounds__(THREADS) fallback_kernel(
    const float* __restrict__ ap, const float* __restrict__ at,
    const float* __restrict__ bp, const float* __restrict__ bt, int n)
{
    if (g_flag == 0) return;
    float m = g_margin;
    double c0 = 0.0, c1 = 0.0;
    const int stride = gridDim.x * blockDim.x;
    for (int i = blockIdx.x * blockDim.x + threadIdx.x; i < n; i += stride) {
        float p = ap[i], t = at[i];
        if (!(fabsf(t - 1.0f) < 1e-5f) && p < m) { double d = (double)m - p; c0 += 0.5 * d * d; }
        p = bp[i]; t = bt[i];
        if (!(fabsf(t - 1.0f) < 1e-5f) && p < m) { double d = (double)m - p; c1 += 0.5 * d * d; }
    }
    __shared__ double sh0[THREADS], sh1[THREADS];
    sh0[threadIdx.x] = c0; sh1[threadIdx.x] = c1;
    __syncthreads();
    for (int o = THREADS / 2; o > 0; o >>= 1) {
        if (threadIdx.x < o) { sh0[threadIdx.x] += sh0[threadIdx.x + o];
                               sh1[threadIdx.x] += sh1[threadIdx.x + o]; }
        __syncthreads();
    }
    if (threadIdx.x == 0) {
        atomicAdd(&g_corr[0], sh0[0]);
        atomicAdd(&g_corr[1], sh1[0]);
    }
}

// ---------------- kernel 4: finalize for fallback path ---------------------------
__global__ void final2_kernel(float* out, double inv_n) {
    if (g_flag == 0) return;
    if (threadIdx.x == 0) {
        double md = (double)g_margin;
        #pragma unroll
        for (int s = 0; s < 2; s++) {
            double sum = 0.5 * g_s2[s] - md * g_s1[s]
                       + 0.5 * md * md * (double)g_k[s] - g_corr[s];
            out[s] = (float)(sum * inv_n);
        }
    }
}

// ---------------- launch ---------------------------------------------------------
extern "C" void kernel_launch(void* const* d_in, const int* in_sizes, int n_in,
                              void* d_out, int out_size)
{
    const float* ap = (const float*)d_in[0];   // asso_predict
    const float* at = (const float*)d_in[1];   // asso_target
    const float* bp = (const float*)d_in[2];   // attr_predict
    const float* bt = (const float*)d_in[3];   // attr_target
    int n = in_sizes[0];
    int n4 = n >> 2;
    int ntail = n & 3;
    double inv_n = 1.0 / (double)n;
    float* out = (float*)d_out;

    init_kernel<<<1, 32>>>();
    pass1_kernel<<<BLOCKS, THREADS>>>(
        (const float4*)ap, (const float4*)at,
        (const float4*)bp, (const float4*)bt, n4, ntail);
    prep_kernel<<<1, 256>>>(out, inv_n);
    fallback_kernel<<<BLOCKS, THREADS>>>(ap, at, bp, bt, n);
    final2_kernel<<<1, 32>>>(out, inv_n);
}

// round 2
// speedup vs baseline: 1.0154x; 1.0154x over previous
#include <cuda_runtime.h>
#include <math.h>

#define THREADS 256
#define BLOCKS  1216          // 152 SMs * 8
#define CAND_CAP (1 << 20)
#define CAND_T   0.00390625f  // 2^-8

// ---------------- device-global scratch (no allocations allowed) ----------------
__device__ double             g_s1[2];       // sum p   over non-positive elems
__device__ double             g_s2[2];       // sum p^2 over non-positive elems
__device__ unsigned long long g_k[2];        // count   of non-positive elems
__device__ unsigned int       g_minkey[2];   // ordered-uint key of min(predict | target==1)
__device__ int                g_candcnt[2];  // # of non-pos elems with p < CAND_T
__device__ int                g_flag;        // 1 => candidate path invalid, use fallback
__device__ double             g_corr[2];     // fallback correction sums
__device__ float              g_margin;
__device__ float              g_cand[2][CAND_CAP];

// ---------------- ordered-uint key for float atomicMin (handles any sign) -------
__device__ __forceinline__ unsigned int fkey(float f) {
    unsigned int b = __float_as_uint(f);
    return (b & 0x80000000u) ? ~b : (b | 0x80000000u);
}
__device__ __forceinline__ float funkey(unsigned int k) {
    unsigned int b = (k & 0x80000000u) ? (k & 0x7fffffffu) : ~k;
    return __uint_as_float(b);
}

// ---------------- kernel 0: reset accumulators (graph replays must be clean) ----
__global__ void init_kernel() {
    if (threadIdx.x == 0) {
        #pragma unroll
        for (int s = 0; s < 2; s++) {
            g_s1[s] = 0.0; g_s2[s] = 0.0; g_k[s] = 0ull;
            g_minkey[s] = 0xFF800000u;   // fkey(+inf)
            g_candcnt[s] = 0;
            g_corr[s] = 0.0;
        }
        g_flag = 0;
        g_margin = 0.0f;
    }
}

// ---------------- kernel 1: single fused pass over all 4 tensors ----------------
// Per lane (tensor s): if target==1 -> track min(predict)
//                      else         -> s1 += p, s2 += p*p, k++, and if p < CAND_T
//                                      append p to candidate buffer.
#define PROC(S, P, T)                                                        \
    do {                                                                     \
        float _p = (P), _t = (T);                                            \
        if (fabsf(_t - 1.0f) < 1e-5f) {                                      \
            mn##S = fminf(mn##S, _p);                                        \
        } else {                                                             \
            s1##S += _p;                                                     \
            s2##S = fmaf(_p, _p, s2##S);                                     \
            k##S++;                                                          \
            if (_p < CAND_T) {                                               \
                int _i = atomicAdd(&g_candcnt[S], 1);                        \
                if (_i < CAND_CAP) g_cand[S][_i] = _p;                       \
            }                                                                \
        }                                                                    \
    } while (0)

__global__ void __launch_bounds__(THREADS) pass1_kernel(
    const float4* __restrict__ ap, const float4* __restrict__ at,
    const float4* __restrict__ bp, const float4* __restrict__ bt,
    int n4, int ntail)
{
    float s10 = 0.f, s20 = 0.f, mn0 = __int_as_float(0x7f800000);
    float s11 = 0.f, s21 = 0.f, mn1 = __int_as_float(0x7f800000);
    int   k0 = 0, k1 = 0;

    const int stride = gridDim.x * blockDim.x;
    for (int i = blockIdx.x * blockDim.x + threadIdx.x; i < n4; i += stride) {
        float4 pa = ap[i], ta = at[i], pb = bp[i], tb = bt[i];
        PROC(0, pa.x, ta.x); PROC(0, pa.y, ta.y);
        PROC(0, pa.z, ta.z); PROC(0, pa.w, ta.w);
        PROC(1, pb.x, tb.x); PROC(1, pb.y, tb.y);
        PROC(1, pb.z, tb.z); PROC(1, pb.w, tb.w);
    }
    // scalar tail (n not divisible by 4)
    if (blockIdx.x == 0 && threadIdx.x < ntail) {
        const float* apf = reinterpret_cast<const float*>(ap);
        const float* atf = reinterpret_cast<const float*>(at);
        const float* bpf = reinterpret_cast<const float*>(bp);
        const float* btf = reinterpret_cast<const float*>(bt);
        int idx = n4 * 4 + threadIdx.x;
        PROC(0, apf[idx], atf[idx]);
        PROC(1, bpf[idx], btf[idx]);
    }

    // ---- warp reduce ----
    #pragma unroll
    for (int o = 16; o > 0; o >>= 1) {
        s10 += __shfl_down_sync(0xffffffffu, s10, o);
        s20 += __shfl_down_sync(0xffffffffu, s20, o);
        k0  += __shfl_down_sync(0xffffffffu, k0,  o);
        mn0  = fminf(mn0, __shfl_down_sync(0xffffffffu, mn0, o));
        s11 += __shfl_down_sync(0xffffffffu, s11, o);
        s21 += __shfl_down_sync(0xffffffffu, s21, o);
        k1  += __shfl_down_sync(0xffffffffu, k1,  o);
        mn1  = fminf(mn1, __shfl_down_sync(0xffffffffu, mn1, o));
    }

    // ---- block reduce across warps ----
    __shared__ float sh_s1[2][THREADS / 32], sh_s2[2][THREADS / 32], sh_mn[2][THREADS / 32];
    __shared__ int   sh_k[2][THREADS / 32];
    int wid = threadIdx.x >> 5, lid = threadIdx.x & 31;
    if (lid == 0) {
        sh_s1[0][wid] = s10; sh_s2[0][wid] = s20; sh_mn[0][wid] = mn0; sh_k[0][wid] = k0;
        sh_s1[1][wid] = s11; sh_s2[1][wid] = s21; sh_mn[1][wid] = mn1; sh_k[1][wid] = k1;
    }
    __syncthreads();
    if (threadIdx.x == 0) {
        #pragma unroll
        for (int s = 0; s < 2; s++) {
            float S1 = 0.f, S2 = 0.f, MN = __int_as_float(0x7f800000);
            int K = 0;
            #pragma unroll
            for (int w = 0; w < THREADS / 32; w++) {
                S1 += sh_s1[s][w]; S2 += sh_s2[s][w];
                K  += sh_k[s][w];  MN  = fminf(MN, sh_mn[s][w]);
            }
            atomicAdd(&g_s1[s], (double)S1);
            atomicAdd(&g_s2[s], (double)S2);
            atomicAdd(&g_k[s],  (unsigned long long)K);
            atomicMin(&g_minkey[s], fkey(MN));
        }
    }
}

// ---------------- kernel 2: compute margin + (usually) final answer -------------
__global__ void __launch_bounds__(256) prep_kernel(float* out, double inv_n) {
    __shared__ double sh[256];
    __shared__ float  sh_m;
    __shared__ int    sh_valid;
    if (threadIdx.x == 0) {
        float sA = fminf(1.0f, funkey(g_minkey[0]));
        float sB = fminf(1.0f, funkey(g_minkey[1]));
        float m  = fminf(sA, sB);
        g_margin = m;
        int valid = (m <= CAND_T) && (g_candcnt[0] <= CAND_CAP) && (g_candcnt[1] <= CAND_CAP);
        g_flag  = valid ? 0 : 1;
        sh_m = m; sh_valid = valid;
    }
    __syncthreads();
    if (!sh_valid) return;    // fallback kernel will finish the job

    float m = sh_m;
    double corr[2];
    #pragma unroll
    for (int s = 0; s < 2; s++) {
        double c = 0.0;
        int cnt = min(g_candcnt[s], CAND_CAP);
        for (int i = threadIdx.x; i < cnt; i += 256) {
            float p = g_cand[s][i];
            if (p < m) { double d = (double)m - (double)p; c += 0.5 * d * d; }
        }
        sh[threadIdx.x] = c;
        __syncthreads();
        for (int o = 128; o > 0; o >>= 1) {
            if (threadIdx.x < o) sh[threadIdx.x] += sh[threadIdx.x + o];
            __syncthreads();
        }
        corr[s] = sh[0];
        __syncthreads();
    }
    if (threadIdx.x == 0) {
        double md = (double)m;
        #pragma unroll
        for (int s = 0; s < 2; s++) {
            double sum = 0.5 * g_s2[s] - md * g_s1[s]
                       + 0.5 * md * md * (double)g_k[s] - corr[s];
            out[s] = (float)(sum * inv_n);
        }
    }
}

// ---------------- kernel 3: exact fallback (early-exits when not needed) --------
__global__ void __launch_bounds__(THREADS) fallback_kernel(
    const float* __restrict__ ap, const float* __restrict__ at,
    const float* __restrict__ bp, const float* __restrict__ bt, int n)
{
    if (g_flag == 0) return;
    float m = g_margin;
    double c0 = 0.0, c1 = 0.0;
    const int stride = gridDim.x * blockDim.x;
    for (int i = blockIdx.x * blockDim.x + threadIdx.x; i < n; i += stride) {
        float p = ap[i], t = at[i];
        if (!(fabsf(t - 1.0f) < 1e-5f) && p < m) { double d = (double)m - p; c0 += 0.5 * d * d; }
        p = bp[i]; t = bt[i];
        if (!(fabsf(t - 1.0f) < 1e-5f) && p < m) { double d = (double)m - p; c1 += 0.5 * d * d; }
    }
    __shared__ double sh0[THREADS], sh1[THREADS];
    sh0[threadIdx.x] = c0; sh1[threadIdx.x] = c1;
    __syncthreads();
    for (int o = THREADS / 2; o > 0; o >>= 1) {
        if (threadIdx.x < o) { sh0[threadIdx.x] += sh0[threadIdx.x + o];
                               sh1[threadIdx.x] += sh1[threadIdx.x + o]; }
        __syncthreads();
    }
    if (threadIdx.x == 0) {
        atomicAdd(&g_corr[0], sh0[0]);
        atomicAdd(&g_corr[1], sh1[0]);
    }
}

// ---------------- kernel 4: finalize for fallback path ---------------------------
__global__ void final2_kernel(float* out, double inv_n) {
    if (g_flag == 0) return;
    if (threadIdx.x == 0) {
        double md = (double)g_margin;
        #pragma unroll
        for (int s = 0; s < 2; s++) {
            double sum = 0.5 * g_s2[s] - md * g_s1[s]
                       + 0.5 * md * md * (double)g_k[s] - g_corr[s];
            out[s] = (float)(sum * inv_n);
        }
    }
}

// ---------------- launch ---------------------------------------------------------
extern "C" void kernel_launch(void* const* d_in, const int* in_sizes, int n_in,
                              void* d_out, int out_size)
{
    const float* ap = (const float*)d_in[0];   // asso_predict
    const float* at = (const float*)d_in[1];   // asso_target
    const float* bp = (const float*)d_in[2];   // attr_predict
    const float* bt = (const float*)d_in[3];   // attr_target
    int n = in_sizes[0];
    int n4 = n >> 2;
    int ntail = n & 3;
    double inv_n = 1.0 / (double)n;
    float* out = (float*)d_out;

    init_kernel<<<1, 32>>>();
    pass1_kernel<<<BLOCKS, THREADS>>>(
        (const float4*)ap, (const float4*)at,
        (const float4*)bp, (const float4*)bt, n4, ntail);
    prep_kernel<<<1, 256>>>(out, inv_n);
    fallback_kernel<<<BLOCKS, THREADS>>>(ap, at, bp, bt, n);
    final2_kernel<<<1, 32>>>(out, inv_n);
}

// round 3
// speedup vs baseline: 3.2365x; 3.1875x over previous
#include <cuda_runtime.h>
#include <math.h>

#define THREADS 256
#define BLOCKS  608          // 152 SMs * 4 blocks -> one wave at ~56 regs/thread

// ---------------- device-global scratch (all identities are 0 => zero-init OK,
// and cleanup_kernel resets to 0 at the end of every replay) ---------------------
__device__ double       g_S1[2];      // sum p      over ALL elems
__device__ double       g_S2[2];      // sum p^2    over ALL elems
__device__ double       g_P1[2];      // sum p*t    (positive-weighted)
__device__ double       g_P2[2];      // sum p^2*t
__device__ double       g_KT[2];      // sum t      (count of positives)
__device__ unsigned int g_maxkey[2];  // max of ~fkey(minpos) ; 0 == "no entries"
__device__ int          g_flag;       // 1 => exact fallback correction needed
__device__ float        g_margin;
__device__ double       g_base[2];
__device__ double       g_corr[2];

// ordered-uint key: p smaller <=> fkey smaller <=> ~fkey larger (atomicMax, identity 0)
__device__ __forceinline__ unsigned int fkey(float f) {
    unsigned int b = __float_as_uint(f);
    return (b & 0x80000000u) ? ~b : (b | 0x80000000u);
}
__device__ __forceinline__ float funkey(unsigned int k) {
    unsigned int b = (k & 0x80000000u) ? (k & 0x7fffffffu) : ~k;
    return __uint_as_float(b);
}

// Branchless per-element accumulate. t is exactly 0.0 or 1.0.
#define ACC(S, P, T)                                             \
    do {                                                         \
        float _p = (P), _t = (T);                                \
        float _q = _p * _p;                                      \
        S1##S += _p;                                             \
        S2##S += _q;                                             \
        P1##S = fmaf(_p, _t, P1##S);                             \
        P2##S = fmaf(_q, _t, P2##S);                             \
        KT##S += _t;                                             \
        MN##S = fminf(MN##S, (_t > 0.5f) ? _p : 1e30f);          \
    } while (0)

#define ACC4(S, PV, TV)                                          \
    do {                                                         \
        ACC(S, (PV).x, (TV).x); ACC(S, (PV).y, (TV).y);          \
        ACC(S, (PV).z, (TV).z); ACC(S, (PV).w, (TV).w);          \
    } while (0)

// ---------------- kernel 1: single branchless fused pass ------------------------
__global__ void __launch_bounds__(THREADS) pass1_kernel(
    const float4* __restrict__ ap, const float4* __restrict__ at,
    const float4* __restrict__ bp, const float4* __restrict__ bt,
    int n4, int ntail)
{
    float S10 = 0.f, S20 = 0.f, P10 = 0.f, P20 = 0.f, KT0 = 0.f, MN0 = 1e30f;
    float S11 = 0.f, S21 = 0.f, P11 = 0.f, P21 = 0.f, KT1 = 0.f, MN1 = 1e30f;

    const int stride = gridDim.x * blockDim.x;
    int i = blockIdx.x * blockDim.x + threadIdx.x;

    // main loop: 2-way unrolled -> 8 independent LDG.128 batched up front
    for (; i + stride < n4; i += 2 * stride) {
        float4 a0 = __ldcs(ap + i);          float4 c0 = __ldcs(at + i);
        float4 b0 = __ldcs(bp + i);          float4 d0 = __ldcs(bt + i);
        float4 a1 = __ldcs(ap + i + stride); float4 c1 = __ldcs(at + i + stride);
        float4 b1 = __ldcs(bp + i + stride); float4 d1 = __ldcs(bt + i + stride);
        ACC4(0, a0, c0); ACC4(1, b0, d0);
        ACC4(0, a1, c1); ACC4(1, b1, d1);
    }
    if (i < n4) {
        float4 a0 = __ldcs(ap + i); float4 c0 = __ldcs(at + i);
        float4 b0 = __ldcs(bp + i); float4 d0 = __ldcs(bt + i);
        ACC4(0, a0, c0); ACC4(1, b0, d0);
    }
    // scalar tail (n % 4)
    if (blockIdx.x == 0 && threadIdx.x < ntail) {
        const float* apf = reinterpret_cast<const float*>(ap);
        const float* atf = reinterpret_cast<const float*>(at);
        const float* bpf = reinterpret_cast<const float*>(bp);
        const float* btf = reinterpret_cast<const float*>(bt);
        int idx = n4 * 4 + threadIdx.x;
        ACC(0, apf[idx], atf[idx]);
        ACC(1, bpf[idx], btf[idx]);
    }

    // ---- warp reduce ----
    #pragma unroll
    for (int o = 16; o > 0; o >>= 1) {
        S10 += __shfl_down_sync(0xffffffffu, S10, o);
        S20 += __shfl_down_sync(0xffffffffu, S20, o);
        P10 += __shfl_down_sync(0xffffffffu, P10, o);
        P20 += __shfl_down_sync(0xffffffffu, P20, o);
        KT0 += __shfl_down_sync(0xffffffffu, KT0, o);
        MN0  = fminf(MN0, __shfl_down_sync(0xffffffffu, MN0, o));
        S11 += __shfl_down_sync(0xffffffffu, S11, o);
        S21 += __shfl_down_sync(0xffffffffu, S21, o);
        P11 += __shfl_down_sync(0xffffffffu, P11, o);
        P21 += __shfl_down_sync(0xffffffffu, P21, o);
        KT1 += __shfl_down_sync(0xffffffffu, KT1, o);
        MN1  = fminf(MN1, __shfl_down_sync(0xffffffffu, MN1, o));
    }

    // ---- block reduce ----
    __shared__ float sh[2][6][THREADS / 32];
    int wid = threadIdx.x >> 5, lid = threadIdx.x & 31;
    if (lid == 0) {
        sh[0][0][wid] = S10; sh[0][1][wid] = S20; sh[0][2][wid] = P10;
        sh[0][3][wid] = P20; sh[0][4][wid] = KT0; sh[0][5][wid] = MN0;
        sh[1][0][wid] = S11; sh[1][1][wid] = S21; sh[1][2][wid] = P11;
        sh[1][3][wid] = P21; sh[1][4][wid] = KT1; sh[1][5][wid] = MN1;
    }
    __syncthreads();
    if (threadIdx.x == 0) {
        #pragma unroll
        for (int s = 0; s < 2; s++) {
            float v0 = 0.f, v1 = 0.f, v2 = 0.f, v3 = 0.f, v4 = 0.f, mn = 1e30f;
            #pragma unroll
            for (int w = 0; w < THREADS / 32; w++) {
                v0 += sh[s][0][w]; v1 += sh[s][1][w]; v2 += sh[s][2][w];
                v3 += sh[s][3][w]; v4 += sh[s][4][w]; mn = fminf(mn, sh[s][5][w]);
            }
            atomicAdd(&g_S1[s], (double)v0);
            atomicAdd(&g_S2[s], (double)v1);
            atomicAdd(&g_P1[s], (double)v2);
            atomicAdd(&g_P2[s], (double)v3);
            atomicAdd(&g_KT[s], (double)v4);
            atomicMax(&g_maxkey[s], ~fkey(mn));
        }
    }
}

// ---------------- kernel 2: margin + closed-form loss (usually final) -----------
__global__ void prep_kernel(float* out, double inv_n, double n_total) {
    if (threadIdx.x != 0) return;
    float sc0, sc1;
    {
        unsigned int k0 = g_maxkey[0], k1 = g_maxkey[1];
        sc0 = (k0 == 0u) ? 1.0f : fminf(1.0f, funkey(~k0));
        sc1 = (k1 == 0u) ? 1.0f : fminf(1.0f, funkey(~k1));
    }
    float m = fminf(sc0, sc1);
    double md = (double)m;

    double base[2], bound[2];
    #pragma unroll
    for (int s = 0; s < 2; s++) {
        double kk = n_total - g_KT[s];        // # non-positive elements (exact)
        double s1 = g_S1[s] - g_P1[s];        // sum p   over non-positive
        double s2 = g_S2[s] - g_P2[s];        // sum p^2 over non-positive
        base[s]  = 0.5 * s2 - md * s1 + 0.5 * md * md * kk;
        bound[s] = 0.5 * md * md * kk;        // >= exact correction for p<m elems
    }
    bool valid = (bound[0] <= 1e-7 * fabs(base[0])) &&
                 (bound[1] <= 1e-7 * fabs(base[1]));
    if (valid) {
        g_flag = 0;
        out[0] = (float)(base[0] * inv_n);
        out[1] = (float)(base[1] * inv_n);
    } else {
        g_flag = 1;
        g_margin = m;
        g_base[0] = base[0];
        g_base[1] = base[1];
    }
}

// ---------------- kernel 3: exact correction (early-exits when not needed) ------
__global__ void __launch_bounds__(THREADS) fallback_kernel(
    const float* __restrict__ ap, const float* __restrict__ at,
    const float* __restrict__ bp, const float* __restrict__ bt, int n)
{
    if (g_flag == 0) return;
    float m = g_margin;
    double c0 = 0.0, c1 = 0.0;
    const int stride = gridDim.x * blockDim.x;
    for (int i = blockIdx.x * blockDim.x + threadIdx.x; i < n; i += stride) {
        float p = ap[i], t = at[i];
        if (!(t > 0.5f) && p < m) { double d = (double)m - (double)p; c0 += 0.5 * d * d; }
        p = bp[i]; t = bt[i];
        if (!(t > 0.5f) && p < m) { double d = (double)m - (double)p; c1 += 0.5 * d * d; }
    }
    __shared__ double sh0[THREADS], sh1[THREADS];
    sh0[threadIdx.x] = c0; sh1[threadIdx.x] = c1;
    __syncthreads();
    for (int o = THREADS / 2; o > 0; o >>= 1) {
        if (threadIdx.x < o) { sh0[threadIdx.x] += sh0[threadIdx.x + o];
                               sh1[threadIdx.x] += sh1[threadIdx.x + o]; }
        __syncthreads();
    }
    if (threadIdx.x == 0) {
        atomicAdd(&g_corr[0], sh0[0]);
        atomicAdd(&g_corr[1], sh1[0]);
    }
}

// ---------------- kernel 4: fallback finalize + reset for next replay -----------
__global__ void cleanup_kernel(float* out, double inv_n) {
    if (threadIdx.x != 0) return;
    if (g_flag) {
        out[0] = (float)((g_base[0] - g_corr[0]) * inv_n);
        out[1] = (float)((g_base[1] - g_corr[1]) * inv_n);
    }
    #pragma unroll
    for (int s = 0; s < 2; s++) {
        g_S1[s] = 0.0; g_S2[s] = 0.0; g_P1[s] = 0.0; g_P2[s] = 0.0; g_KT[s] = 0.0;
        g_maxkey[s] = 0u; g_base[s] = 0.0; g_corr[s] = 0.0;
    }
    g_flag = 0;
    g_margin = 0.0f;
}

// ---------------- launch ---------------------------------------------------------
extern "C" void kernel_launch(void* const* d_in, const int* in_sizes, int n_in,
                              void* d_out, int out_size)
{
    const float* ap = (const float*)d_in[0];   // asso_predict
    const float* at = (const float*)d_in[1];   // asso_target
    const float* bp = (const float*)d_in[2];   // attr_predict
    const float* bt = (const float*)d_in[3];   // attr_target
    int n = in_sizes[0];
    int n4 = n >> 2;
    int ntail = n & 3;
    double inv_n = 1.0 / (double)n;
    float* out = (float*)d_out;

    pass1_kernel<<<BLOCKS, THREADS>>>(
        (const float4*)ap, (const float4*)at,
        (const float4*)bp, (const float4*)bt, n4, ntail);
    prep_kernel<<<1, 32>>>(out, inv_n, (double)n);
    fallback_kernel<<<BLOCKS, THREADS>>>(ap, at, bp, bt, n);
    cleanup_kernel<<<1, 32>>>(out, inv_n);
}

// round 4
// speedup vs baseline: 3.3576x; 1.0374x over previous
#include <cuda_runtime.h>
#include <math.h>

#define THREADS 256
#define BLOCKS  608          // 152 SMs * 4 blocks

// ---------------- device-global scratch (zero-init; last block resets to 0
// after every replay, so the graph is replay-clean) -------------------------------
__device__ double       g_S1[2];      // sum p      over ALL elems
__device__ double       g_S2[2];      // sum p^2    over ALL elems
__device__ double       g_P1[2];      // sum p*t
__device__ double       g_P2[2];      // sum p^2*t
__device__ double       g_KT[2];      // sum t (count of positives)
__device__ unsigned int g_maxkey[2];  // max of ~fkey(min positive p); identity 0
__device__ unsigned int g_count;      // blocks-done counter

// ordered-uint key: p smaller <=> fkey smaller <=> ~fkey larger (atomicMax, id 0)
__device__ __forceinline__ unsigned int fkey(float f) {
    unsigned int b = __float_as_uint(f);
    return (b & 0x80000000u) ? ~b : (b | 0x80000000u);
}
__device__ __forceinline__ float funkey(unsigned int k) {
    unsigned int b = (k & 0x80000000u) ? (k & 0x7fffffffu) : ~k;
    return __uint_as_float(b);
}

// Branchless per-element accumulate. t is exactly 0.0 or 1.0.
#define ACC(S, P, T)                                             \
    do {                                                         \
        float _p = (P), _t = (T);                                \
        float _q = _p * _p;                                      \
        S1##S += _p;                                             \
        S2##S += _q;                                             \
        P1##S = fmaf(_p, _t, P1##S);                             \
        P2##S = fmaf(_q, _t, P2##S);                             \
        KT##S += _t;                                             \
        MN##S = fminf(MN##S, (_t > 0.5f) ? _p : 1e30f);          \
    } while (0)

#define ACC4(S, PV, TV)                                          \
    do {                                                         \
        ACC(S, (PV).x, (TV).x); ACC(S, (PV).y, (TV).y);          \
        ACC(S, (PV).z, (TV).z); ACC(S, (PV).w, (TV).w);          \
    } while (0)

// ---------------- single fused kernel --------------------------------------------
__global__ void __launch_bounds__(THREADS) union_loss_kernel(
    const float4* __restrict__ ap4, const float4* __restrict__ at4,
    const float4* __restrict__ bp4, const float4* __restrict__ bt4,
    float* __restrict__ out, int n4, int ntail, double inv_n, double n_total)
{
    float S10 = 0.f, S20 = 0.f, P10 = 0.f, P20 = 0.f, KT0 = 0.f, MN0 = 1e30f;
    float S11 = 0.f, S21 = 0.f, P11 = 0.f, P21 = 0.f, KT1 = 0.f, MN1 = 1e30f;

    const int stride = gridDim.x * blockDim.x;
    int i = blockIdx.x * blockDim.x + threadIdx.x;

    // main loop: 2-way unrolled -> 8 independent LDG.128 batched up front
    for (; i + stride < n4; i += 2 * stride) {
        float4 a0 = __ldcs(ap4 + i);          float4 c0 = __ldcs(at4 + i);
        float4 b0 = __ldcs(bp4 + i);          float4 d0 = __ldcs(bt4 + i);
        float4 a1 = __ldcs(ap4 + i + stride); float4 c1 = __ldcs(at4 + i + stride);
        float4 b1 = __ldcs(bp4 + i + stride); float4 d1 = __ldcs(bt4 + i + stride);
        ACC4(0, a0, c0); ACC4(1, b0, d0);
        ACC4(0, a1, c1); ACC4(1, b1, d1);
    }
    if (i < n4) {
        float4 a0 = __ldcs(ap4 + i); float4 c0 = __ldcs(at4 + i);
        float4 b0 = __ldcs(bp4 + i); float4 d0 = __ldcs(bt4 + i);
        ACC4(0, a0, c0); ACC4(1, b0, d0);
    }
    // scalar tail (n % 4)
    const float* ap = reinterpret_cast<const float*>(ap4);
    const float* at = reinterpret_cast<const float*>(at4);
    const float* bp = reinterpret_cast<const float*>(bp4);
    const float* bt = reinterpret_cast<const float*>(bt4);
    if (blockIdx.x == 0 && threadIdx.x < ntail) {
        int idx = n4 * 4 + threadIdx.x;
        ACC(0, ap[idx], at[idx]);
        ACC(1, bp[idx], bt[idx]);
    }

    // ---- warp reduce ----
    #pragma unroll
    for (int o = 16; o > 0; o >>= 1) {
        S10 += __shfl_down_sync(0xffffffffu, S10, o);
        S20 += __shfl_down_sync(0xffffffffu, S20, o);
        P10 += __shfl_down_sync(0xffffffffu, P10, o);
        P20 += __shfl_down_sync(0xffffffffu, P20, o);
        KT0 += __shfl_down_sync(0xffffffffu, KT0, o);
        MN0  = fminf(MN0, __shfl_down_sync(0xffffffffu, MN0, o));
        S11 += __shfl_down_sync(0xffffffffu, S11, o);
        S21 += __shfl_down_sync(0xffffffffu, S21, o);
        P11 += __shfl_down_sync(0xffffffffu, P11, o);
        P21 += __shfl_down_sync(0xffffffffu, P21, o);
        KT1 += __shfl_down_sync(0xffffffffu, KT1, o);
        MN1  = fminf(MN1, __shfl_down_sync(0xffffffffu, MN1, o));
    }

    // ---- block reduce ----
    __shared__ float sh[2][6][THREADS / 32];
    int wid = threadIdx.x >> 5, lid = threadIdx.x & 31;
    if (lid == 0) {
        sh[0][0][wid] = S10; sh[0][1][wid] = S20; sh[0][2][wid] = P10;
        sh[0][3][wid] = P20; sh[0][4][wid] = KT0; sh[0][5][wid] = MN0;
        sh[1][0][wid] = S11; sh[1][1][wid] = S21; sh[1][2][wid] = P11;
        sh[1][3][wid] = P21; sh[1][4][wid] = KT1; sh[1][5][wid] = MN1;
    }
    __syncthreads();
    if (threadIdx.x == 0) {
        #pragma unroll
        for (int s = 0; s < 2; s++) {
            float v0 = 0.f, v1 = 0.f, v2 = 0.f, v3 = 0.f, v4 = 0.f, mn = 1e30f;
            #pragma unroll
            for (int w = 0; w < THREADS / 32; w++) {
                v0 += sh[s][0][w]; v1 += sh[s][1][w]; v2 += sh[s][2][w];
                v3 += sh[s][3][w]; v4 += sh[s][4][w]; mn = fminf(mn, sh[s][5][w]);
            }
            atomicAdd(&g_S1[s], (double)v0);
            atomicAdd(&g_S2[s], (double)v1);
            atomicAdd(&g_P1[s], (double)v2);
            atomicAdd(&g_P2[s], (double)v3);
            atomicAdd(&g_KT[s], (double)v4);
            atomicMax(&g_maxkey[s], ~fkey(mn));
        }
    }

    // ---- last-block finalize (threadfence-reduction pattern) ----
    __shared__ int sh_last;
    __shared__ float sh_margin;
    __shared__ int sh_need_fallback;
    __shared__ double sh_base0, sh_base1;
    if (threadIdx.x == 0) {
        __threadfence();
        unsigned int done = atomicAdd(&g_count, 1u);
        sh_last = (done == gridDim.x - 1u);
    }
    __syncthreads();
    if (!sh_last) return;

    if (threadIdx.x == 0) {
        __threadfence();   // acquire: other blocks' atomics visible (L2)
        float sc0 = fminf(1.0f, funkey(~g_maxkey[0]));
        float sc1 = fminf(1.0f, funkey(~g_maxkey[1]));
        float m   = fminf(sc0, sc1);
        double md = (double)m;

        double base[2], bound[2];
        #pragma unroll
        for (int s = 0; s < 2; s++) {
            double kk = n_total - g_KT[s];     // # non-positive elements (exact)
            double s1 = g_S1[s] - g_P1[s];     // sum p   over non-positive
            double s2 = g_S2[s] - g_P2[s];     // sum p^2 over non-positive
            base[s]  = 0.5 * s2 - md * s1 + 0.5 * md * md * kk;
            bound[s] = 0.5 * md * md * kk;     // >= exact correction from p<m elems
        }
        bool valid = (bound[0] <= 1e-7 * fabs(base[0])) &&
                     (bound[1] <= 1e-7 * fabs(base[1]));
        sh_need_fallback = !valid;
        sh_margin = m;
        sh_base0 = base[0];
        sh_base1 = base[1];
        if (valid) {
            out[0] = (float)(base[0] * inv_n);
            out[1] = (float)(base[1] * inv_n);
        }
        // reset globals for next graph replay
        #pragma unroll
        for (int s = 0; s < 2; s++) {
            g_S1[s] = 0.0; g_S2[s] = 0.0; g_P1[s] = 0.0;
            g_P2[s] = 0.0; g_KT[s] = 0.0; g_maxkey[s] = 0u;
        }
        g_count = 0u;
    }
    __syncthreads();
    if (!sh_need_fallback) return;

    // ---- exact correction fallback (single block; never taken on this data) ----
    {
        float m = sh_margin;
        int n = n4 * 4 + ntail;
        double c0 = 0.0, c1 = 0.0;
        for (int j = threadIdx.x; j < n; j += THREADS) {
            float p = ap[j], t = at[j];
            if (!(t > 0.5f) && p < m) { double d = (double)m - (double)p; c0 += 0.5 * d * d; }
            p = bp[j]; t = bt[j];
            if (!(t > 0.5f) && p < m) { double d = (double)m - (double)p; c1 += 0.5 * d * d; }
        }
        __shared__ double shd0[THREADS], shd1[THREADS];
        shd0[threadIdx.x] = c0; shd1[threadIdx.x] = c1;
        __syncthreads();
        for (int o = THREADS / 2; o > 0; o >>= 1) {
            if (threadIdx.x < o) { shd0[threadIdx.x] += shd0[threadIdx.x + o];
                                   shd1[threadIdx.x] += shd1[threadIdx.x + o]; }
            __syncthreads();
        }
        if (threadIdx.x == 0) {
            out[0] = (float)((sh_base0 - shd0[0]) * inv_n);
            out[1] = (float)((sh_base1 - shd1[0]) * inv_n);
        }
    }
}

// ---------------- launch ---------------------------------------------------------
extern "C" void kernel_launch(void* const* d_in, const int* in_sizes, int n_in,
                              void* d_out, int out_size)
{
    const float* ap = (const float*)d_in[0];   // asso_predict
    const float* at = (const float*)d_in[1];   // asso_target
    const float* bp = (const float*)d_in[2];   // attr_predict
    const float* bt = (const float*)d_in[3];   // attr_target
    int n = in_sizes[0];
    int n4 = n >> 2;
    int ntail = n & 3;
    double inv_n = 1.0 / (double)n;
    float* out = (float*)d_out;

    union_loss_kernel<<<BLOCKS, THREADS>>>(
        (const float4*)ap, (const float4*)at,
        (const float4*)bp, (const float4*)bt,
        out, n4, ntail, inv_n, (double)n);
}

// round 5
// speedup vs baseline: 3.4054x; 1.0142x over previous
#include <cuda_runtime.h>
#include <math.h>

#define THREADS 256
#define BLOCKS  760          // 152 SMs * 5 blocks (reg-file limit at 44 regs) = 1 wave

// ---------------- device-global scratch (zero-init; last block resets to 0
// after every replay, so the graph is replay-clean) -------------------------------
__device__ double       g_S1[2];      // sum p      over ALL elems
__device__ double       g_S2[2];      // sum p^2    over ALL elems
__device__ double       g_P1[2];      // sum p*t
__device__ double       g_P2[2];      // sum p^2*t
__device__ double       g_KT[2];      // sum t (count of positives)
__device__ unsigned int g_maxkey[2];  // max of ~fkey(min positive p); identity 0
__device__ unsigned int g_count;      // blocks-done counter

// ordered-uint key: p smaller <=> fkey smaller <=> ~fkey larger (atomicMax, id 0)
__device__ __forceinline__ unsigned int fkey(float f) {
    unsigned int b = __float_as_uint(f);
    return (b & 0x80000000u) ? ~b : (b | 0x80000000u);
}
__device__ __forceinline__ float funkey(unsigned int k) {
    unsigned int b = (k & 0x80000000u) ? (k & 0x7fffffffu) : ~k;
    return __uint_as_float(b);
}

// Branchless per-element accumulate. t is exactly 0.0 or 1.0.
#define ACC(S, P, T)                                             \
    do {                                                         \
        float _p = (P), _t = (T);                                \
        float _q = _p * _p;                                      \
        S1##S += _p;                                             \
        S2##S += _q;                                             \
        P1##S = fmaf(_p, _t, P1##S);                             \
        P2##S = fmaf(_q, _t, P2##S);                             \
        KT##S += _t;                                             \
        MN##S = fminf(MN##S, (_t > 0.5f) ? _p : 1e30f);          \
    } while (0)

#define ACC4(S, PV, TV)                                          \
    do {                                                         \
        ACC(S, (PV).x, (TV).x); ACC(S, (PV).y, (TV).y);          \
        ACC(S, (PV).z, (TV).z); ACC(S, (PV).w, (TV).w);          \
    } while (0)

// ---------------- single fused kernel --------------------------------------------
__global__ void __launch_bounds__(THREADS) union_loss_kernel(
    const float4* __restrict__ ap4, const float4* __restrict__ at4,
    const float4* __restrict__ bp4, const float4* __restrict__ bt4,
    float* __restrict__ out, int n4, int ntail, double inv_n, double n_total)
{
    float S10 = 0.f, S20 = 0.f, P10 = 0.f, P20 = 0.f, KT0 = 0.f, MN0 = 1e30f;
    float S11 = 0.f, S21 = 0.f, P11 = 0.f, P21 = 0.f, KT1 = 0.f, MN1 = 1e30f;

    const int stride = gridDim.x * blockDim.x;
    int i = blockIdx.x * blockDim.x + threadIdx.x;

    // main loop: 2-way unrolled -> 8 independent LDG.128 batched up front
    for (; i + stride < n4; i += 2 * stride) {
        float4 a0 = __ldcs(ap4 + i);          float4 c0 = __ldcs(at4 + i);
        float4 b0 = __ldcs(bp4 + i);          float4 d0 = __ldcs(bt4 + i);
        float4 a1 = __ldcs(ap4 + i + stride); float4 c1 = __ldcs(at4 + i + stride);
        float4 b1 = __ldcs(bp4 + i + stride); float4 d1 = __ldcs(bt4 + i + stride);
        ACC4(0, a0, c0); ACC4(1, b0, d0);
        ACC4(0, a1, c1); ACC4(1, b1, d1);
    }
    if (i < n4) {
        float4 a0 = __ldcs(ap4 + i); float4 c0 = __ldcs(at4 + i);
        float4 b0 = __ldcs(bp4 + i); float4 d0 = __ldcs(bt4 + i);
        ACC4(0, a0, c0); ACC4(1, b0, d0);
    }
    // scalar tail (n % 4)
    const float* ap = reinterpret_cast<const float*>(ap4);
    const float* at = reinterpret_cast<const float*>(at4);
    const float* bp = reinterpret_cast<const float*>(bp4);
    const float* bt = reinterpret_cast<const float*>(bt4);
    if (blockIdx.x == 0 && threadIdx.x < ntail) {
        int idx = n4 * 4 + threadIdx.x;
        ACC(0, ap[idx], at[idx]);
        ACC(1, bp[idx], bt[idx]);
    }

    // ---- warp reduce ----
    #pragma unroll
    for (int o = 16; o > 0; o >>= 1) {
        S10 += __shfl_down_sync(0xffffffffu, S10, o);
        S20 += __shfl_down_sync(0xffffffffu, S20, o);
        P10 += __shfl_down_sync(0xffffffffu, P10, o);
        P20 += __shfl_down_sync(0xffffffffu, P20, o);
        KT0 += __shfl_down_sync(0xffffffffu, KT0, o);
        MN0  = fminf(MN0, __shfl_down_sync(0xffffffffu, MN0, o));
        S11 += __shfl_down_sync(0xffffffffu, S11, o);
        S21 += __shfl_down_sync(0xffffffffu, S21, o);
        P11 += __shfl_down_sync(0xffffffffu, P11, o);
        P21 += __shfl_down_sync(0xffffffffu, P21, o);
        KT1 += __shfl_down_sync(0xffffffffu, KT1, o);
        MN1  = fminf(MN1, __shfl_down_sync(0xffffffffu, MN1, o));
    }

    // ---- block reduce ----
    __shared__ float sh[2][6][THREADS / 32];
    int wid = threadIdx.x >> 5, lid = threadIdx.x & 31;
    if (lid == 0) {
        sh[0][0][wid] = S10; sh[0][1][wid] = S20; sh[0][2][wid] = P10;
        sh[0][3][wid] = P20; sh[0][4][wid] = KT0; sh[0][5][wid] = MN0;
        sh[1][0][wid] = S11; sh[1][1][wid] = S21; sh[1][2][wid] = P11;
        sh[1][3][wid] = P21; sh[1][4][wid] = KT1; sh[1][5][wid] = MN1;
    }
    __syncthreads();
    if (threadIdx.x == 0) {
        #pragma unroll
        for (int s = 0; s < 2; s++) {
            float v0 = 0.f, v1 = 0.f, v2 = 0.f, v3 = 0.f, v4 = 0.f, mn = 1e30f;
            #pragma unroll
            for (int w = 0; w < THREADS / 32; w++) {
                v0 += sh[s][0][w]; v1 += sh[s][1][w]; v2 += sh[s][2][w];
                v3 += sh[s][3][w]; v4 += sh[s][4][w]; mn = fminf(mn, sh[s][5][w]);
            }
            atomicAdd(&g_S1[s], (double)v0);
            atomicAdd(&g_S2[s], (double)v1);
            atomicAdd(&g_P1[s], (double)v2);
            atomicAdd(&g_P2[s], (double)v3);
            atomicAdd(&g_KT[s], (double)v4);
            atomicMax(&g_maxkey[s], ~fkey(mn));
        }
    }

    // ---- last-block finalize (threadfence-reduction pattern) ----
    __shared__ int sh_last;
    __shared__ float sh_margin;
    __shared__ int sh_need_fallback;
    __shared__ double sh_base0, sh_base1;
    if (threadIdx.x == 0) {
        __threadfence();
        unsigned int done = atomicAdd(&g_count, 1u);
        sh_last = (done == gridDim.x - 1u);
    }
    __syncthreads();
    if (!sh_last) return;

    if (threadIdx.x == 0) {
        __threadfence();   // acquire: other blocks' atomics visible (L2)
        float sc0 = fminf(1.0f, funkey(~g_maxkey[0]));
        float sc1 = fminf(1.0f, funkey(~g_maxkey[1]));
        float m   = fminf(sc0, sc1);
        double md = (double)m;

        double base[2], bound[2];
        #pragma unroll
        for (int s = 0; s < 2; s++) {
            double kk = n_total - g_KT[s];     // # non-positive elements (exact)
            double s1 = g_S1[s] - g_P1[s];     // sum p   over non-positive
            double s2 = g_S2[s] - g_P2[s];     // sum p^2 over non-positive
            base[s]  = 0.5 * s2 - md * s1 + 0.5 * md * md * kk;
            bound[s] = 0.5 * md * md * kk;     // >= exact correction from p<m elems
        }
        bool valid = (bound[0] <= 1e-7 * fabs(base[0])) &&
                     (bound[1] <= 1e-7 * fabs(base[1]));
        sh_need_fallback = !valid;
        sh_margin = m;
        sh_base0 = base[0];
        sh_base1 = base[1];
        if (valid) {
            out[0] = (float)(base[0] * inv_n);
            out[1] = (float)(base[1] * inv_n);
        }
        // reset globals for next graph replay
        #pragma unroll
        for (int s = 0; s < 2; s++) {
            g_S1[s] = 0.0; g_S2[s] = 0.0; g_P1[s] = 0.0;
            g_P2[s] = 0.0; g_KT[s] = 0.0; g_maxkey[s] = 0u;
        }
        g_count = 0u;
    }
    __syncthreads();
    if (!sh_need_fallback) return;

    // ---- exact correction fallback (single block; never taken on this data) ----
    {
        float m = sh_margin;
        int n = n4 * 4 + ntail;
        double c0 = 0.0, c1 = 0.0;
        for (int j = threadIdx.x; j < n; j += THREADS) {
            float p = ap[j], t = at[j];
            if (!(t > 0.5f) && p < m) { double d = (double)m - (double)p; c0 += 0.5 * d * d; }
            p = bp[j]; t = bt[j];
            if (!(t > 0.5f) && p < m) { double d = (double)m - (double)p; c1 += 0.5 * d * d; }
        }
        __shared__ double shd0[THREADS], shd1[THREADS];
        shd0[threadIdx.x] = c0; shd1[threadIdx.x] = c1;
        __syncthreads();
        for (int o = THREADS / 2; o > 0; o >>= 1) {
            if (threadIdx.x < o) { shd0[threadIdx.x] += shd0[threadIdx.x + o];
                                   shd1[threadIdx.x] += shd1[threadIdx.x + o]; }
            __syncthreads();
        }
        if (threadIdx.x == 0) {
            out[0] = (float)((sh_base0 - shd0[0]) * inv_n);
            out[1] = (float)((sh_base1 - shd1[0]) * inv_n);
        }
    }
}

// ---------------- launch ---------------------------------------------------------
extern "C" void kernel_launch(void* const* d_in, const int* in_sizes, int n_in,
                              void* d_out, int out_size)
{
    const float* ap = (const float*)d_in[0];   // asso_predict
    const float* at = (const float*)d_in[1];   // asso_target
    const float* bp = (const float*)d_in[2];   // attr_predict
    const float* bt = (const float*)d_in[3];   // attr_target
    int n = in_sizes[0];
    int n4 = n >> 2;
    int ntail = n & 3;
    double inv_n = 1.0 / (double)n;
    float* out = (float*)d_out;

    union_loss_kernel<<<BLOCKS, THREADS>>>(
        (const float4*)ap, (const float4*)at,
        (const float4*)bp, (const float4*)bt,
        out, n4, ntail, inv_n, (double)n);
}

// round 6
// speedup vs baseline: 3.5028x; 1.0286x over previous
#include <cuda_runtime.h>
#include <math.h>

#define THREADS 256
#define BPSM    6
#define BLOCKS  (152 * BPSM)   // one full wave at 6 blocks/SM (regs forced <= 42)

// ---------------- device-global scratch (zero-init; last block resets to 0
// after every replay, so the graph is replay-clean) -------------------------------
__device__ double       g_S1[2];      // sum p   over non-positive elems (via pu)
__device__ double       g_S2[2];      // sum p^2 over non-positive elems (via pu^2)
__device__ double       g_KT[2];      // sum t (count of positives)
__device__ unsigned int g_maxkey[2];  // max of ~fkey(min positive p); identity 0
__device__ unsigned int g_count;      // blocks-done counter

// ordered-uint key: p smaller <=> fkey smaller <=> ~fkey larger (atomicMax, id 0)
__device__ __forceinline__ unsigned int fkey(float f) {
    unsigned int b = __float_as_uint(f);
    return (b & 0x80000000u) ? ~b : (b | 0x80000000u);
}
__device__ __forceinline__ float funkey(unsigned int k) {
    unsigned int b = (k & 0x80000000u) ? (k & 0x7fffffffu) : ~k;
    return __uint_as_float(b);
}

// Branchless per-element accumulate. t is exactly 0.0 or 1.0, so
// pu = p*(1-t) = fmaf(-p, t, p) is EXACT (either p or 0.0).
#define ACC(S, P, T)                                             \
    do {                                                         \
        float _p = (P), _t = (T);                                \
        float _pu = fmaf(-_p, _t, _p);                           \
        S1##S += _pu;                                            \
        S2##S = fmaf(_pu, _pu, S2##S);                           \
        KT##S += _t;                                             \
        MN##S = fminf(MN##S, (_t > 0.5f) ? _p : 1e30f);          \
    } while (0)

#define ACC4(S, PV, TV)                                          \
    do {                                                         \
        ACC(S, (PV).x, (TV).x); ACC(S, (PV).y, (TV).y);          \
        ACC(S, (PV).z, (TV).z); ACC(S, (PV).w, (TV).w);          \
    } while (0)

// ---------------- single fused kernel --------------------------------------------
__global__ void __launch_bounds__(THREADS, BPSM) union_loss_kernel(
    const float4* __restrict__ ap4, const float4* __restrict__ at4,
    const float4* __restrict__ bp4, const float4* __restrict__ bt4,
    float* __restrict__ out, int n4, int ntail, double inv_n, double n_total)
{
    float S10 = 0.f, S20 = 0.f, KT0 = 0.f, MN0 = 1e30f;
    float S11 = 0.f, S21 = 0.f, KT1 = 0.f, MN1 = 1e30f;

    const int stride = gridDim.x * blockDim.x;
    int i = blockIdx.x * blockDim.x + threadIdx.x;

    // main loop: 2-way unrolled -> 8 independent LDG.128 batched up front
    for (; i + stride < n4; i += 2 * stride) {
        float4 a0 = __ldcs(ap4 + i);          float4 c0 = __ldcs(at4 + i);
        float4 b0 = __ldcs(bp4 + i);          float4 d0 = __ldcs(bt4 + i);
        float4 a1 = __ldcs(ap4 + i + stride); float4 c1 = __ldcs(at4 + i + stride);
        float4 b1 = __ldcs(bp4 + i + stride); float4 d1 = __ldcs(bt4 + i + stride);
        ACC4(0, a0, c0); ACC4(1, b0, d0);
        ACC4(0, a1, c1); ACC4(1, b1, d1);
    }
    if (i < n4) {
        float4 a0 = __ldcs(ap4 + i); float4 c0 = __ldcs(at4 + i);
        float4 b0 = __ldcs(bp4 + i); float4 d0 = __ldcs(bt4 + i);
        ACC4(0, a0, c0); ACC4(1, b0, d0);
    }
    // scalar tail (n % 4)
    const float* ap = reinterpret_cast<const float*>(ap4);
    const float* at = reinterpret_cast<const float*>(at4);
    const float* bp = reinterpret_cast<const float*>(bp4);
    const float* bt = reinterpret_cast<const float*>(bt4);
    if (blockIdx.x == 0 && threadIdx.x < ntail) {
        int idx = n4 * 4 + threadIdx.x;
        ACC(0, ap[idx], at[idx]);
        ACC(1, bp[idx], bt[idx]);
    }

    // ---- warp reduce ----
    #pragma unroll
    for (int o = 16; o > 0; o >>= 1) {
        S10 += __shfl_down_sync(0xffffffffu, S10, o);
        S20 += __shfl_down_sync(0xffffffffu, S20, o);
        KT0 += __shfl_down_sync(0xffffffffu, KT0, o);
        MN0  = fminf(MN0, __shfl_down_sync(0xffffffffu, MN0, o));
        S11 += __shfl_down_sync(0xffffffffu, S11, o);
        S21 += __shfl_down_sync(0xffffffffu, S21, o);
        KT1 += __shfl_down_sync(0xffffffffu, KT1, o);
        MN1  = fminf(MN1, __shfl_down_sync(0xffffffffu, MN1, o));
    }

    // ---- block reduce ----
    __shared__ float sh[2][4][THREADS / 32];
    int wid = threadIdx.x >> 5, lid = threadIdx.x & 31;
    if (lid == 0) {
        sh[0][0][wid] = S10; sh[0][1][wid] = S20;
        sh[0][2][wid] = KT0; sh[0][3][wid] = MN0;
        sh[1][0][wid] = S11; sh[1][1][wid] = S21;
        sh[1][2][wid] = KT1; sh[1][3][wid] = MN1;
    }
    __syncthreads();
    if (threadIdx.x == 0) {
        #pragma unroll
        for (int s = 0; s < 2; s++) {
            float v0 = 0.f, v1 = 0.f, v2 = 0.f, mn = 1e30f;
            #pragma unroll
            for (int w = 0; w < THREADS / 32; w++) {
                v0 += sh[s][0][w]; v1 += sh[s][1][w];
                v2 += sh[s][2][w]; mn = fminf(mn, sh[s][3][w]);
            }
            atomicAdd(&g_S1[s], (double)v0);
            atomicAdd(&g_S2[s], (double)v1);
            atomicAdd(&g_KT[s], (double)v2);
            atomicMax(&g_maxkey[s], ~fkey(mn));
        }
    }

    // ---- last-block finalize (threadfence-reduction pattern) ----
    __shared__ int sh_last;
    __shared__ float sh_margin;
    __shared__ int sh_need_fallback;
    __shared__ double sh_base0, sh_base1;
    if (threadIdx.x == 0) {
        __threadfence();
        unsigned int done = atomicAdd(&g_count, 1u);
        sh_last = (done == gridDim.x - 1u);
    }
    __syncthreads();
    if (!sh_last) return;

    if (threadIdx.x == 0) {
        __threadfence();   // acquire: other blocks' atomics visible (L2)
        float sc0 = fminf(1.0f, funkey(~g_maxkey[0]));
        float sc1 = fminf(1.0f, funkey(~g_maxkey[1]));
        float m   = fminf(sc0, sc1);
        double md = (double)m;

        double base[2], bound[2];
        #pragma unroll
        for (int s = 0; s < 2; s++) {
            double kk = n_total - g_KT[s];     // # non-positive elements (exact)
            double s1 = g_S1[s];               // sum p   over non-positive
            double s2 = g_S2[s];               // sum p^2 over non-positive
            base[s]  = 0.5 * s2 - md * s1 + 0.5 * md * md * kk;
            bound[s] = 0.5 * md * md * kk;     // >= exact correction from p<m elems
        }
        bool valid = (bound[0] <= 1e-7 * fabs(base[0])) &&
                     (bound[1] <= 1e-7 * fabs(base[1]));
        sh_need_fallback = !valid;
        sh_margin = m;
        sh_base0 = base[0];
        sh_base1 = base[1];
        if (valid) {
            out[0] = (float)(base[0] * inv_n);
            out[1] = (float)(base[1] * inv_n);
        }
        // reset globals for next graph replay
        #pragma unroll
        for (int s = 0; s < 2; s++) {
            g_S1[s] = 0.0; g_S2[s] = 0.0; g_KT[s] = 0.0; g_maxkey[s] = 0u;
        }
        g_count = 0u;
    }
    __syncthreads();
    if (!sh_need_fallback) return;

    // ---- exact correction fallback (single block; never taken on this data) ----
    {
        float m = sh_margin;
        int n = n4 * 4 + ntail;
        double c0 = 0.0, c1 = 0.0;
        for (int j = threadIdx.x; j < n; j += THREADS) {
            float p = ap[j], t = at[j];
            if (!(t > 0.5f) && p < m) { double d = (double)m - (double)p; c0 += 0.5 * d * d; }
            p = bp[j]; t = bt[j];
            if (!(t > 0.5f) && p < m) { double d = (double)m - (double)p; c1 += 0.5 * d * d; }
        }
        __shared__ double shd0[THREADS], shd1[THREADS];
        shd0[threadIdx.x] = c0; shd1[threadIdx.x] = c1;
        __syncthreads();
        for (int o = THREADS / 2; o > 0; o >>= 1) {
            if (threadIdx.x < o) { shd0[threadIdx.x] += shd0[threadIdx.x + o];
                                   shd1[threadIdx.x] += shd1[threadIdx.x + o]; }
            __syncthreads();
        }
        if (threadIdx.x == 0) {
            out[0] = (float)((sh_base0 - shd0[0]) * inv_n);
            out[1] = (float)((sh_base1 - shd1[0]) * inv_n);
        }
    }
}

// ---------------- launch ---------------------------------------------------------
extern "C" void kernel_launch(void* const* d_in, const int* in_sizes, int n_in,
                              void* d_out, int out_size)
{
    const float* ap = (const float*)d_in[0];   // asso_predict
    const float* at = (const float*)d_in[1];   // asso_target
    const float* bp = (const float*)d_in[2];   // attr_predict
    const float* bt = (const float*)d_in[3];   // attr_target
    int n = in_sizes[0];
    int n4 = n >> 2;
    int ntail = n & 3;
    double inv_n = 1.0 / (double)n;
    float* out = (float*)d_out;

    union_loss_kernel<<<BLOCKS, THREADS>>>(
        (const float4*)ap, (const float4*)at,
        (const float4*)bp, (const float4*)bt,
        out, n4, ntail, inv_n, (double)n);
}